// round 3
// baseline (speedup 1.0000x reference)
#include <cuda_runtime.h>

// NetG: encoder GRU -> +noise -> decoder GRU -> FC head. Persistent kernel.
// 512 thr/block (16 warps/SM), f32x2 batch-pair FFMA, j-paired SMEM layouts,
// duplicated-pair weights (48B cells, bank-rotated), h ping-pong in L2,
// per-batch-group grid barriers.

#define BSZ 512
#define TSZ 256
#define HSZ 256
#define NBLK 128
#define NTHR 512
#define BT 64
#define IT 16

typedef unsigned long long u64;

// global h ping-pong, layout [j2:128][gbp:256][jp:2][b2:2]
__device__ float g_h[2][131072];
__device__ unsigned g_cnt[8 * 32];
__device__ unsigned g_genv[8 * 32];

__device__ __forceinline__ float2 unpack2(u64 v) {
    float2 f; asm("mov.b64 {%0, %1}, %2;" : "=f"(f.x), "=f"(f.y) : "l"(v)); return f;
}
__device__ __forceinline__ void ffma2(u64 &d, u64 a, u64 b) {
    asm("fma.rn.f32x2 %0, %1, %2, %0;" : "+l"(d) : "l"(a), "l"(b));
}
__device__ __forceinline__ float sigf(float x) {
    return __fdividef(1.0f, 1.0f + __expf(-x));
}
__device__ __forceinline__ float tanhf_(float x) {
    return 1.0f - __fdividef(2.0f, __expf(2.0f * x) + 1.0f);
}

__device__ __forceinline__ void group_sync(int grp, unsigned &gen) {
    __syncthreads();
    if (threadIdx.x == 0) {
        unsigned* cnt = &g_cnt[grp * 32];
        unsigned* gv  = &g_genv[grp * 32];
        unsigned g = gen;
        __threadfence();
        if (atomicAdd(cnt, 1u) == 15u) {
            *cnt = 0;
            __threadfence();
            atomicExch(gv, g + 1);
        } else {
            while (*(volatile unsigned*)gv != g + 1) { }
        }
        __threadfence();
        gen = g + 1;
    }
    __syncthreads();
}

// Stage W_hh slice: cell(j2,il) = 12 floats {rr_j, zz_j, nn_j, rr_j1, zz_j1, nn_j1}
__device__ __forceinline__ void stage_whh(const float* __restrict__ W,
                                          float* __restrict__ w_s, int iblk, int tid) {
    #pragma unroll
    for (int k = 0; k < 24; ++k) {          // 128 j2 * 16 il * 6 slots = 12288
        int idx = tid + k * NTHR;
        int cell = idx / 6;
        int s = idx - cell * 6;
        int g = s >> 1, jp = s & 1;
        int ilx = cell & 15, j2 = cell >> 4;
        float wv = W[(g * HSZ + iblk * IT + ilx) * HSZ + j2 * 2 + jp];
        *(float2*)(w_s + (j2 * 16 + ilx) * 12 + jp * 6 + g * 2) = make_float2(wv, wv);
    }
}

__device__ __forceinline__ void project_tile(
    const float* __restrict__ h_s, const float* __restrict__ wfc_s,
    float* __restrict__ out, int b0, int iblk, int tid, int tstep,
    float bf0, float bf1, float bf2)
{
    // 4 warps: each projects one local batch (iblk picks which 4 of 64)
    int bl = iblk * 4 + (tid >> 5);
    int lane = tid & 31;
    int cofs = (bl >> 1) * 4 + (bl & 1);
    float a0 = 0.f, a1 = 0.f, a2 = 0.f;
    #pragma unroll
    for (int k = 0; k < 8; ++k) {
        int j = lane + k * 32;
        float hv = h_s[(j >> 1) * 132 + (j & 1) * 2 + cofs];
        a0 = fmaf(hv, wfc_s[j],       a0);
        a1 = fmaf(hv, wfc_s[256 + j], a1);
        a2 = fmaf(hv, wfc_s[512 + j], a2);
    }
    #pragma unroll
    for (int o = 16; o > 0; o >>= 1) {
        a0 += __shfl_xor_sync(0xffffffffu, a0, o);
        a1 += __shfl_xor_sync(0xffffffffu, a1, o);
        a2 += __shfl_xor_sync(0xffffffffu, a2, o);
    }
    if (lane == 0) {
        int base = ((b0 + bl) * TSZ + tstep) * 3;
        out[base + 0] = a0 + bf0;
        out[base + 1] = a1 + bf1;
        out[base + 2] = a2 + bf2;
    }
}

extern "C" __global__ void __launch_bounds__(NTHR, 1)
netg_kernel(const float* __restrict__ X_p, const float* __restrict__ X_f,
            const float* __restrict__ noise,
            const float* __restrict__ Wih_e, const float* __restrict__ Whh_e,
            const float* __restrict__ bih_e, const float* __restrict__ bhh_e,
            const float* __restrict__ Wih_d, const float* __restrict__ Whh_d,
            const float* __restrict__ bih_d, const float* __restrict__ bhh_d,
            const float* __restrict__ Wfc,   const float* __restrict__ bfc,
            float* __restrict__ out)
{
    extern __shared__ float smem[];
    float* h_s   = smem;                   // 128*132 = 16896 floats, [j2](33 float4)
    float* w_s   = h_s + 128 * 132;        // 24576 floats (12-float cells)
    float* wfc_s = w_s + 24576;            // 768
    float* x_s   = wfc_s + 768;            // 192
    float* wih_s = x_s + 192;              // 2*144
    float* bih_s = wih_s + 288;            // 2*48
    float* bhh_s = bih_s + 96;             // 2*48

    const int tid  = threadIdx.x;
    const int lane = tid & 31;
    const int wrp  = tid >> 5;
    const int iblk = blockIdx.x & 15;
    const int bblk = blockIdx.x >> 4;
    const int b0   = bblk * BT;

    // warp = 8 bpair x 4 consecutive il
    const int bpair = (wrp & 3) * 8 + (lane & 7);     // 0..31
    const int il    = (wrp >> 2) * 4 + (lane >> 3);   // 0..15
    const int ig    = iblk * IT + il;

    // ---- stage encoder W_hh + FC + per-il params ----
    stage_whh(Whh_e, w_s, iblk, tid);
    for (int k = tid; k < 768; k += NTHR) wfc_s[k] = Wfc[k];
    for (int k = tid; k < 288; k += NTHR) {
        int p = k / 144, rem = k - p * 144;
        int ii = rem / 9, q = rem - ii * 9;
        int g = q / 3, d = q - g * 3;
        wih_s[k] = (p ? Wih_d : Wih_e)[(g * HSZ + iblk * IT + ii) * 3 + d];
    }
    for (int k = tid; k < 96; k += NTHR) {
        int p = k / 48, rem = k - p * 48;
        int ii = rem / 3, g = rem - ii * 3;
        bih_s[k] = (p ? bih_d : bih_e)[g * HSZ + iblk * IT + ii];
        bhh_s[k] = (p ? bhh_d : bhh_e)[g * HSZ + iblk * IT + ii];
    }
    const float bf0 = bfc[0], bf1 = bfc[1], bf2 = bfc[2];

    // ---- zero h buffer 0 ----
    *(float2*)(&g_h[0][blockIdx.x * 1024 + tid * 2]) = make_float2(0.f, 0.f);

    unsigned gen = *(volatile unsigned*)&g_genv[bblk * 32];
    group_sync(bblk, gen);

    int cur = 0;
    for (int t = 0; t < 2 * TSZ; ++t) {
        const bool enc = (t < TSZ);
        const int tt = enc ? t : t - TSZ;
        const int phase = enc ? 0 : 1;

        if (t == TSZ) stage_whh(Whh_d, w_s, iblk, tid);

        // stage x_t (decoder input = right-shifted X_f)
        if (tid < 192) {
            int bl = tid / 3, d = tid - bl * 3;
            float v = 0.f;
            if (enc)          v = X_p[(b0 + bl) * (TSZ * 3) + tt * 3 + d];
            else if (tt > 0)  v = X_f[(b0 + bl) * (TSZ * 3) + (tt - 1) * 3 + d];
            x_s[bl * 3 + d] = v;
        }
        // stage h tile: straight f4 copy (global layout already j-paired)
        {
            const float4* src = (const float4*)&g_h[cur][0] + (b0 >> 1);
            float4* dst4 = (float4*)h_s;
            #pragma unroll
            for (int k = 0; k < 8; ++k) {
                int idx = tid + k * NTHR;
                int j2 = idx >> 5, bp = idx & 31;
                dst4[j2 * 33 + bp] = src[j2 * 256 + bp];
            }
        }
        __syncthreads();

        // fused output head (decoder): project Y_{tt-1} from current h_s
        if (!enc && tt >= 1 && tid < 128)
            project_tile(h_s, wfc_s, out, b0, iblk, tid, tt - 1, bf0, bf1, bf2);

        // GEMM: 6 independent f32x2 accumulators (even/odd j)
        u64 aR0 = 0, aZ0 = 0, aN0 = 0, aR1 = 0, aZ1 = 0, aN1 = 0;
        const float* hp = h_s + bpair * 4;
        const float* wp = w_s + il * 12;
        #pragma unroll 4
        for (int j2 = 0; j2 < 128; ++j2) {
            const ulonglong2 hv = *(const ulonglong2*)(hp + j2 * 132);
            const ulonglong2 w0 = *(const ulonglong2*)(wp + j2 * 192);
            const ulonglong2 w1 = *(const ulonglong2*)(wp + j2 * 192 + 4);
            const ulonglong2 w2 = *(const ulonglong2*)(wp + j2 * 192 + 8);
            ffma2(aR0, w0.x, hv.x);
            ffma2(aZ0, w0.y, hv.x);
            ffma2(aN0, w1.x, hv.x);
            ffma2(aR1, w1.y, hv.y);
            ffma2(aZ1, w2.x, hv.y);
            ffma2(aN1, w2.y, hv.y);
        }
        float2 R0 = unpack2(aR0), R1 = unpack2(aR1);
        float2 Z0 = unpack2(aZ0), Z1 = unpack2(aZ1);
        float2 N0 = unpack2(aN0), N1 = unpack2(aN1);
        float Rb[2] = {R0.x + R1.x, R0.y + R1.y};
        float Zb[2] = {Z0.x + Z1.x, Z0.y + Z1.y};
        float Nb[2] = {N0.x + N1.x, N0.y + N1.y};

        // gates + h update (PyTorch GRU r,z,n; b_hh_n inside r*( ))
        const float* wi = wih_s + phase * 144 + il * 9;
        const float* bi = bih_s + phase * 48 + il * 3;
        const float* bh = bhh_s + phase * 48 + il * 3;
        const float bhr = bh[0], bhz = bh[1], bhn = bh[2];
        const bool add_noise = enc && (tt == TSZ - 1);
        float hnew[2];
        #pragma unroll
        for (int b2 = 0; b2 < 2; ++b2) {
            int bl = bpair * 2 + b2;
            float x0 = x_s[bl * 3 + 0], x1 = x_s[bl * 3 + 1], x2 = x_s[bl * 3 + 2];
            float xr = bi[0] + wi[0] * x0 + wi[1] * x1 + wi[2] * x2;
            float xz = bi[1] + wi[3] * x0 + wi[4] * x1 + wi[5] * x2;
            float xn = bi[2] + wi[6] * x0 + wi[7] * x1 + wi[8] * x2;
            float r = sigf(xr + Rb[b2] + bhr);
            float z = sigf(xz + Zb[b2] + bhz);
            float n = tanhf_(xn + r * (Nb[b2] + bhn));
            float hprev = hp[(ig >> 1) * 132 + (ig & 1) * 2 + b2];
            float hn = n + z * (hprev - n);
            if (add_noise) hn += noise[(b0 + bl) * HSZ + ig];
            hnew[b2] = hn;
        }
        *(float2*)(&g_h[cur ^ 1][(ig >> 1) * 1024 + ((b0 >> 1) + bpair) * 4 + (ig & 1) * 2])
            = make_float2(hnew[0], hnew[1]);

        cur ^= 1;
        group_sync(bblk, gen);
    }

    // epilogue: project final decoder output Y_{T-1}
    {
        const float4* src = (const float4*)&g_h[cur][0] + (b0 >> 1);
        float4* dst4 = (float4*)h_s;
        #pragma unroll
        for (int k = 0; k < 8; ++k) {
            int idx = tid + k * NTHR;
            int j2 = idx >> 5, bp = idx & 31;
            dst4[j2 * 33 + bp] = src[j2 * 256 + bp];
        }
        __syncthreads();
        if (tid < 128)
            project_tile(h_s, wfc_s, out, b0, iblk, tid, TSZ - 1, bf0, bf1, bf2);
    }
}

extern "C" void kernel_launch(void* const* d_in, const int* in_sizes, int n_in,
                              void* d_out, int out_size) {
    const float* X_p   = (const float*)d_in[0];
    const float* X_f   = (const float*)d_in[1];
    const float* noise = (const float*)d_in[2];
    const float* Wih_e = (const float*)d_in[3];
    const float* Whh_e = (const float*)d_in[4];
    const float* bih_e = (const float*)d_in[5];
    const float* bhh_e = (const float*)d_in[6];
    const float* Wih_d = (const float*)d_in[7];
    const float* Whh_d = (const float*)d_in[8];
    const float* bih_d = (const float*)d_in[9];
    const float* bhh_d = (const float*)d_in[10];
    const float* Wfc   = (const float*)d_in[11];
    const float* bfc   = (const float*)d_in[12];
    float* out = (float*)d_out;

    size_t smem_bytes = (size_t)(128 * 132 + 24576 + 768 + 192 + 288 + 96 + 96)
                        * sizeof(float);
    cudaFuncSetAttribute(netg_kernel, cudaFuncAttributeMaxDynamicSharedMemorySize,
                         (int)smem_bytes);

    netg_kernel<<<NBLK, NTHR, smem_bytes>>>(
        X_p, X_f, noise, Wih_e, Whh_e, bih_e, bhh_e,
        Wih_d, Whh_d, bih_d, bhh_d, Wfc, bfc, out);
}

// round 4
// speedup vs baseline: 1.1321x; 1.1321x over previous
#include <cuda_runtime.h>

// NetG: encoder GRU -> +noise -> decoder GRU -> FC head. Persistent kernel.
// 512 thr/block (16 warps/SM), scalar FFMA (f32x2 proven useless on sm_103a fp32 pipe),
// thread = 2 batches x 1 hidden row, both GRU weights SMEM-resident,
// h ping-pong in L2, per-batch-group grid barriers.

#define BSZ 512
#define TSZ 256
#define HSZ 256
#define NBLK 128
#define NTHR 512
#define BT 64
#define IT 16
#define HPAD 72   // h_s row stride in floats

__device__ float g_h[2][HSZ * BSZ];    // [buf][j * BSZ + b]
__device__ unsigned g_cnt[8 * 32];
__device__ unsigned g_genv[8 * 32];

__device__ __forceinline__ float sigf(float x) {
    return __fdividef(1.0f, 1.0f + __expf(-x));
}
__device__ __forceinline__ float tanhf_(float x) {
    return 1.0f - __fdividef(2.0f, __expf(2.0f * x) + 1.0f);
}

__device__ __forceinline__ void group_sync(int grp, unsigned &gen) {
    __syncthreads();
    if (threadIdx.x == 0) {
        unsigned* cnt = &g_cnt[grp * 32];
        unsigned* gv  = &g_genv[grp * 32];
        unsigned g = gen;
        __threadfence();
        if (atomicAdd(cnt, 1u) == 15u) {
            *cnt = 0;
            __threadfence();
            atomicExch(gv, g + 1);
        } else {
            while (*(volatile unsigned*)gv != g + 1) { }
        }
        __threadfence();
        gen = g + 1;
    }
    __syncthreads();
}

// stage one GRU's W_hh slice: w_s[(j*16+il)*4] = {r, z, n, 0}
__device__ __forceinline__ void stage_whh(const float* __restrict__ W,
                                          float* __restrict__ ws, int iblk, int tid) {
    #pragma unroll
    for (int k = 0; k < 24; ++k) {          // 3 g * 16 il * 256 j = 12288 / 512 thr
        int idx = tid + k * NTHR;
        int g = idx >> 12;
        int rem = idx & 4095;
        int i2 = rem >> 8;
        int j  = rem & 255;
        ws[(j * 16 + i2) * 4 + g] = W[(g * HSZ + iblk * IT + i2) * HSZ + j];
    }
}

__device__ __forceinline__ void project_tile(
    const float* __restrict__ h_s, const float* __restrict__ wfc_s,
    float* __restrict__ out, int b0, int iblk, int tid, int tstep,
    float bf0, float bf1, float bf2)
{
    // 4 warps: each projects one local batch (iblk picks which 4 of 64)
    int bl = iblk * 4 + (tid >> 5);
    int lane = tid & 31;
    float a0 = 0.f, a1 = 0.f, a2 = 0.f;
    #pragma unroll
    for (int k = 0; k < 8; ++k) {
        int j = lane + k * 32;
        float hv = h_s[j * HPAD + bl];
        a0 = fmaf(hv, wfc_s[j],       a0);
        a1 = fmaf(hv, wfc_s[256 + j], a1);
        a2 = fmaf(hv, wfc_s[512 + j], a2);
    }
    #pragma unroll
    for (int o = 16; o > 0; o >>= 1) {
        a0 += __shfl_xor_sync(0xffffffffu, a0, o);
        a1 += __shfl_xor_sync(0xffffffffu, a1, o);
        a2 += __shfl_xor_sync(0xffffffffu, a2, o);
    }
    if (lane == 0) {
        int base = ((b0 + bl) * TSZ + tstep) * 3;
        out[base + 0] = a0 + bf0;
        out[base + 1] = a1 + bf1;
        out[base + 2] = a2 + bf2;
    }
}

extern "C" __global__ void __launch_bounds__(NTHR, 1)
netg_kernel(const float* __restrict__ X_p, const float* __restrict__ X_f,
            const float* __restrict__ noise,
            const float* __restrict__ Wih_e, const float* __restrict__ Whh_e,
            const float* __restrict__ bih_e, const float* __restrict__ bhh_e,
            const float* __restrict__ Wih_d, const float* __restrict__ Whh_d,
            const float* __restrict__ bih_d, const float* __restrict__ bhh_d,
            const float* __restrict__ Wfc,   const float* __restrict__ bfc,
            float* __restrict__ out)
{
    extern __shared__ float smem[];
    float* h_s   = smem;                   // 256*72 = 18432 floats
    float* we_s  = h_s + 256 * HPAD;       // 16384 floats [j][il]{r,z,n,0}
    float* wd_s  = we_s + 16384;           // 16384
    float* wfc_s = wd_s + 16384;           // 768
    float* x_s   = wfc_s + 768;            // 192
    float* wih_s = x_s + 192;              // 2*144
    float* bih_s = wih_s + 288;            // 2*48
    float* bhh_s = bih_s + 96;             // 2*48

    const int tid  = threadIdx.x;
    const int lane = tid & 31;
    const int wrp  = tid >> 5;
    const int iblk = blockIdx.x & 15;
    const int bblk = blockIdx.x >> 4;
    const int b0   = bblk * BT;

    // warp = 16 bpair x 2 il : h read = one contiguous 128B wavefront,
    // w read = 2 distinct 16B cells (1 wavefront)
    const int bpair = ((wrp >> 3) << 4) | (lane & 15);  // 0..31 (2 batches each)
    const int il    = ((wrp & 7) << 1) | (lane >> 4);   // 0..15
    const int ig    = iblk * IT + il;

    // ---- stage both GRUs' W_hh + FC + per-il params ----
    stage_whh(Whh_e, we_s, iblk, tid);
    stage_whh(Whh_d, wd_s, iblk, tid);
    for (int k = tid; k < 768; k += NTHR) wfc_s[k] = Wfc[k];
    for (int k = tid; k < 288; k += NTHR) {
        int p = k / 144, rem = k - p * 144;
        int ii = rem / 9, q = rem - ii * 9;
        int g = q / 3, d = q - g * 3;
        wih_s[k] = (p ? Wih_d : Wih_e)[(g * HSZ + iblk * IT + ii) * 3 + d];
    }
    for (int k = tid; k < 96; k += NTHR) {
        int p = k / 48, rem = k - p * 48;
        int ii = rem / 3, g = rem - ii * 3;
        bih_s[k] = (p ? bih_d : bih_e)[g * HSZ + iblk * IT + ii];
        bhh_s[k] = (p ? bhh_d : bhh_e)[g * HSZ + iblk * IT + ii];
    }
    const float bf0 = bfc[0], bf1 = bfc[1], bf2 = bfc[2];

    // ---- zero h buffer 0 (encoder h0 = 0) ----
    *(float2*)(&g_h[0][blockIdx.x * 1024 + tid * 2]) = make_float2(0.f, 0.f);

    unsigned gen = *(volatile unsigned*)&g_genv[bblk * 32];
    group_sync(bblk, gen);

    int cur = 0;
    for (int t = 0; t < 2 * TSZ; ++t) {
        const bool enc = (t < TSZ);
        const int tt = enc ? t : t - TSZ;
        const int phase = enc ? 0 : 1;

        // stage x_t (decoder input = right-shifted X_f; step 0 -> zeros)
        if (tid < 192) {
            int bl = tid / 3, d = tid - bl * 3;
            float v = 0.f;
            if (enc)          v = X_p[(b0 + bl) * (TSZ * 3) + tt * 3 + d];
            else if (tt > 0)  v = X_f[(b0 + bl) * (TSZ * 3) + (tt - 1) * 3 + d];
            x_s[bl * 3 + d] = v;
        }
        // stage h tile: g_h[cur][j][b0..b0+63] -> h_s (HPAD-float rows)
        {
            const float4* src = (const float4*)&g_h[cur][0] + (b0 >> 2);
            float4* dst4 = (float4*)h_s;
            #pragma unroll
            for (int k = 0; k < 8; ++k) {
                int idx = tid + k * NTHR;
                int j = idx >> 4, b4 = idx & 15;
                dst4[j * (HPAD / 4) + b4] = src[j * (BSZ / 4) + b4];
            }
        }
        __syncthreads();

        // fused output head (decoder): project Y_{tt-1} from current h_s
        if (!enc && tt >= 1 && tid < 128)
            project_tile(h_s, wfc_s, out, b0, iblk, tid, tt - 1, bf0, bf1, bf2);

        // GEMM: gh[g][b] = sum_j h[b,j] * W_hh[g,j]  (2 batches x 3 gates)
        float aR0 = 0.f, aR1 = 0.f, aZ0 = 0.f, aZ1 = 0.f, aN0 = 0.f, aN1 = 0.f;
        const float* hp = h_s + bpair * 2;
        const float* wp = (phase ? wd_s : we_s) + il * 4;
        #pragma unroll 8
        for (int j = 0; j < HSZ; ++j) {
            const float2 hv = *(const float2*)(hp + j * HPAD);
            const float4 wv = *(const float4*)(wp + j * 64);
            aR0 = fmaf(wv.x, hv.x, aR0);
            aR1 = fmaf(wv.x, hv.y, aR1);
            aZ0 = fmaf(wv.y, hv.x, aZ0);
            aZ1 = fmaf(wv.y, hv.y, aZ1);
            aN0 = fmaf(wv.z, hv.x, aN0);
            aN1 = fmaf(wv.z, hv.y, aN1);
        }
        float Rb[2] = {aR0, aR1};
        float Zb[2] = {aZ0, aZ1};
        float Nb[2] = {aN0, aN1};

        // gates + h update (PyTorch GRU r,z,n; b_hh_n inside r*( ))
        const float* wi = wih_s + phase * 144 + il * 9;
        const float* bi = bih_s + phase * 48 + il * 3;
        const float* bh = bhh_s + phase * 48 + il * 3;
        const float bhr = bh[0], bhz = bh[1], bhn = bh[2];
        const bool add_noise = enc && (tt == TSZ - 1);
        float hnew[2];
        #pragma unroll
        for (int b2 = 0; b2 < 2; ++b2) {
            int bl = bpair * 2 + b2;
            float x0 = x_s[bl * 3 + 0], x1 = x_s[bl * 3 + 1], x2 = x_s[bl * 3 + 2];
            float xr = bi[0] + wi[0] * x0 + wi[1] * x1 + wi[2] * x2;
            float xz = bi[1] + wi[3] * x0 + wi[4] * x1 + wi[5] * x2;
            float xn = bi[2] + wi[6] * x0 + wi[7] * x1 + wi[8] * x2;
            float r = sigf(xr + Rb[b2] + bhr);
            float z = sigf(xz + Zb[b2] + bhz);
            float n = tanhf_(xn + r * (Nb[b2] + bhn));
            float hprev = h_s[ig * HPAD + bl];
            float hn = n + z * (hprev - n);
            if (add_noise) hn += noise[(b0 + bl) * HSZ + ig];
            hnew[b2] = hn;
        }
        *(float2*)(&g_h[cur ^ 1][ig * BSZ + b0 + bpair * 2]) =
            make_float2(hnew[0], hnew[1]);

        cur ^= 1;
        group_sync(bblk, gen);
    }

    // epilogue: project final decoder output Y_{T-1}
    {
        const float4* src = (const float4*)&g_h[cur][0] + (b0 >> 2);
        float4* dst4 = (float4*)h_s;
        #pragma unroll
        for (int k = 0; k < 8; ++k) {
            int idx = tid + k * NTHR;
            int j = idx >> 4, b4 = idx & 15;
            dst4[j * (HPAD / 4) + b4] = src[j * (BSZ / 4) + b4];
        }
        __syncthreads();
        if (tid < 128)
            project_tile(h_s, wfc_s, out, b0, iblk, tid, TSZ - 1, bf0, bf1, bf2);
    }
}

extern "C" void kernel_launch(void* const* d_in, const int* in_sizes, int n_in,
                              void* d_out, int out_size) {
    const float* X_p   = (const float*)d_in[0];
    const float* X_f   = (const float*)d_in[1];
    const float* noise = (const float*)d_in[2];
    const float* Wih_e = (const float*)d_in[3];
    const float* Whh_e = (const float*)d_in[4];
    const float* bih_e = (const float*)d_in[5];
    const float* bhh_e = (const float*)d_in[6];
    const float* Wih_d = (const float*)d_in[7];
    const float* Whh_d = (const float*)d_in[8];
    const float* bih_d = (const float*)d_in[9];
    const float* bhh_d = (const float*)d_in[10];
    const float* Wfc   = (const float*)d_in[11];
    const float* bfc   = (const float*)d_in[12];
    float* out = (float*)d_out;

    size_t smem_bytes = (size_t)(256 * HPAD + 2 * 16384 + 768 + 192 + 288 + 96 + 96)
                        * sizeof(float);
    cudaFuncSetAttribute(netg_kernel, cudaFuncAttributeMaxDynamicSharedMemorySize,
                         (int)smem_bytes);

    netg_kernel<<<NBLK, NTHR, smem_bytes>>>(
        X_p, X_f, noise, Wih_e, Whh_e, bih_e, bhh_e,
        Wih_d, Whh_d, bih_d, bhh_d, Wfc, bfc, out);
}

// round 6
// speedup vs baseline: 2.4062x; 2.1255x over previous
#include <cuda_runtime.h>
#include <cuda_bf16.h>
#include <cstdint>

// NetG: encoder GRU -> +noise -> decoder GRU -> FC head.
// Persistent kernel using legacy tensor-core mma.sync.m16n8k16 (bf16 x3 split,
// fp32 accumulate) since tcgen05 is unavailable at the harness's PTX target.
// 128 CTAs = 8 batch-groups(64) x 16 hidden-blocks(16). B (weights) lives in
// registers per warp; A (split-bf16 h) ping-pongs through L2 and is restaged
// into swizzled SMEM each step for ldmatrix. h state is exact fp32 in regs.

#define TSZ 256
#define HSZ 256
#define BSZ 512
#define NCTA 128
#define NTHR 256

// smem byte offsets
#define A_HI 0                // 64 x 512B swizzled bf16 (Ah)
#define A_LO 32768            // Al
#define CBUF 65536            // float [m stride 212][kw stride 52][n 48]
#define WIHB 119808           // 48 x float4 {w0,w1,w2,bih}
#define BHHO 120576           // 48 floats bhh
#define WFCO 120768           // 48 floats wfc (3 x 16)
#define SMEM_BYTES 120960

__device__ __nv_bfloat16 g_hbf[2][2][BSZ * HSZ];  // [hi/lo][buf][b*256+j]
__device__ float g_yp[2][NCTA][64][4];            // head partials
__device__ unsigned g_cnt[8 * 32];
__device__ unsigned g_genv[8 * 32];

__device__ __forceinline__ uint32_t smem_u32(const void* p) {
    uint32_t a;
    asm("{ .reg .u64 t; cvta.to.shared.u64 t, %1; cvt.u32.u64 %0, t; }"
        : "=r"(a) : "l"(p));
    return a;
}
__device__ __forceinline__ void ldm4(uint32_t* r, uint32_t addr) {
    asm volatile("ldmatrix.sync.aligned.m8n8.x4.shared.b16 {%0,%1,%2,%3}, [%4];"
        : "=r"(r[0]), "=r"(r[1]), "=r"(r[2]), "=r"(r[3]) : "r"(addr));
}
__device__ __forceinline__ void mma16816(float* c, const uint32_t* a,
                                         uint32_t b0, uint32_t b1) {
    asm volatile(
        "mma.sync.aligned.m16n8k16.row.col.f32.bf16.bf16.f32 "
        "{%0,%1,%2,%3}, {%4,%5,%6,%7}, {%8,%9}, {%0,%1,%2,%3};"
        : "+f"(c[0]), "+f"(c[1]), "+f"(c[2]), "+f"(c[3])
        : "r"(a[0]), "r"(a[1]), "r"(a[2]), "r"(a[3]), "r"(b0), "r"(b1));
}
__device__ __forceinline__ float sigf(float x) {
    return __fdividef(1.0f, 1.0f + __expf(-x));
}
__device__ __forceinline__ float tanhf_(float x) {
    return 1.0f - __fdividef(2.0f, __expf(2.0f * x) + 1.0f);
}

__device__ __forceinline__ void group_sync(int grp, unsigned &gen) {
    __syncthreads();
    if (threadIdx.x == 0) {
        unsigned* cnt = &g_cnt[grp * 32];
        unsigned* gv  = &g_genv[grp * 32];
        unsigned g = gen;
        __threadfence();
        if (atomicAdd(cnt, 1u) == 15u) {
            *cnt = 0;
            __threadfence();
            atomicExch(gv, g + 1);
        } else {
            while (*(volatile unsigned*)gv != g + 1) { }
        }
        __threadfence();
        gen = g + 1;
    }
    __syncthreads();
}

// Build this warp's B fragments (weights) in registers, split hi/lo bf16.
// Warp covers n = 0..47 (full), k = kw*64 .. kw*64+63.
__device__ __forceinline__ void stage_Bregs(
    const float* __restrict__ W, uint32_t Bh[6][4][2], uint32_t Bl[6][4][2],
    int ib, int kw, int lane)
{
    const int nr = lane >> 2, kc = (lane & 3) * 2;
    #pragma unroll
    for (int nt = 0; nt < 6; ++nt) {
        int n = nt * 8 + nr;
        int g = n >> 4, c = n & 15;
        const float* row = W + (g * HSZ + ib * 16 + c) * HSZ;
        #pragma unroll
        for (int kt = 0; kt < 4; ++kt) {
            #pragma unroll
            for (int rg = 0; rg < 2; ++rg) {
                int kk = kw * 64 + kt * 16 + rg * 8 + kc;
                float2 w = *(const float2*)(row + kk);
                __nv_bfloat16 h0 = __float2bfloat16(w.x);
                __nv_bfloat16 h1 = __float2bfloat16(w.y);
                __nv_bfloat16 l0 = __float2bfloat16(w.x - __bfloat162float(h0));
                __nv_bfloat16 l1 = __float2bfloat16(w.y - __bfloat162float(h1));
                Bh[nt][kt][rg] = (uint32_t)__bfloat16_as_ushort(h0)
                               | ((uint32_t)__bfloat16_as_ushort(h1) << 16);
                Bl[nt][kt][rg] = (uint32_t)__bfloat16_as_ushort(l0)
                               | ((uint32_t)__bfloat16_as_ushort(l1) << 16);
            }
        }
    }
}

extern "C" __global__ void __launch_bounds__(NTHR, 1)
netg_mma(const float* __restrict__ X_p, const float* __restrict__ X_f,
         const float* __restrict__ noise,
         const float* __restrict__ Wih_e, const float* __restrict__ Whh_e,
         const float* __restrict__ bih_e, const float* __restrict__ bhh_e,
         const float* __restrict__ Wih_d, const float* __restrict__ Whh_d,
         const float* __restrict__ bih_d, const float* __restrict__ bhh_d,
         const float* __restrict__ Wfc,   const float* __restrict__ bfc,
         float* __restrict__ out)
{
    extern __shared__ char smc[];
    const uint32_t smb = smem_u32(smc);
    const int tid = threadIdx.x, lane = tid & 31, wid = tid >> 5;
    const int bb = blockIdx.x >> 4, ib = blockIdx.x & 15;
    const int mw = wid & 1, kw = wid >> 1;

    float4* wihb_s = (float4*)(smc + WIHB);
    float*  bhh_s  = (float*)(smc + BHHO);
    float*  wfc_s  = (float*)(smc + WFCO);

    // ---- weights into registers / params into SMEM (encoder phase) ----
    uint32_t Bh[6][4][2], Bl[6][4][2];
    stage_Bregs(Whh_e, Bh, Bl, ib, kw, lane);
    if (tid < 48) {
        int g = tid >> 4, c = tid & 15;
        int row = g * HSZ + ib * 16 + c;
        wihb_s[tid] = make_float4(Wih_e[row * 3], Wih_e[row * 3 + 1],
                                  Wih_e[row * 3 + 2], bih_e[row]);
        bhh_s[tid] = bhh_e[row];
        wfc_s[tid] = Wfc[g * HSZ + ib * 16 + c];   // g doubles as d (3x16)
    }

    // epilogue thread mapping: m = tid>>2 (batch local), iq = tid&3 (4 hid each)
    const int m_e = tid >> 2, iq = tid & 3;
    const int bg = bb * 64 + m_e;

    // zero h buffer 0 (encoder h0 = 0); must be redone every launch
    {
        uint2 z = make_uint2(0u, 0u);
        *(uint2*)(&g_hbf[0][0][bg * HSZ + ib * 16 + iq * 4]) = z;
        *(uint2*)(&g_hbf[1][0][bg * HSZ + ib * 16 + iq * 4]) = z;
    }
    float hprev[4] = {0.f, 0.f, 0.f, 0.f};

    // ldmatrix per-lane address bases
    const int lgrp = lane >> 3, lrow = lane & 7;
    const int r0 = mw * 32 + ((lgrp & 1) << 3) + lrow;
    const int segoff = lgrp >> 1;
    const uint32_t rbh0 = smb + A_HI + r0 * 512;
    const uint32_t rbh1 = rbh0 + 16 * 512;
    const uint32_t rbl0 = smb + A_LO + r0 * 512;
    const uint32_t rbl1 = rbl0 + 16 * 512;

    unsigned gen = *(volatile unsigned*)&g_genv[bb * 32];
    group_sync(bb, gen);

    for (int t = 0; t < 2 * TSZ; ++t) {
        const bool enc = t < TSZ;
        const int tt = enc ? t : t - TSZ;
        const int cur = t & 1, nxt = cur ^ 1;

        if (t == TSZ) {   // switch to decoder weights
            stage_Bregs(Whh_d, Bh, Bl, ib, kw, lane);
            if (tid < 48) {
                int g = tid >> 4, c = tid & 15;
                int row = g * HSZ + ib * 16 + c;
                wihb_s[tid] = make_float4(Wih_d[row * 3], Wih_d[row * 3 + 1],
                                          Wih_d[row * 3 + 2], bih_d[row]);
                bhh_s[tid] = bhh_d[row];
            }
        }

        // reduce previous decoder step's head partials (one CTA per group)
        if (t > TSZ && ib == 0 && tid < 192) {
            int bl = tid / 3, d = tid - bl * 3;
            float s2 = bfc[d];
            #pragma unroll
            for (int p = 0; p < 16; ++p)
                s2 += g_yp[(t & 1) ^ 1][bb * 16 + p][bl][d];
            out[((bb * 64 + bl) * TSZ + (tt - 1)) * 3 + d] = s2;
        }

        // stage A (split h) from global into swizzled SMEM
        #pragma unroll
        for (int p = 0; p < 2; ++p) {
            const __nv_bfloat16* src = g_hbf[p][cur] + bb * 64 * HSZ;
            char* db = smc + (p ? A_LO : A_HI);
            #pragma unroll
            for (int i2 = 0; i2 < 8; ++i2) {
                int idx = tid + i2 * NTHR;
                int mm = idx >> 5, s = idx & 31;
                uint4 v = *(const uint4*)(src + mm * HSZ + s * 8);
                *(uint4*)(db + mm * 512 + ((s ^ (mm & 7)) << 4)) = v;
            }
        }
        __syncthreads();

        // ---- tensor-core GEMM: C[m 0..63][n 0..47] partial over K-quarter ----
        float c[2][6][4];
        #pragma unroll
        for (int a = 0; a < 2; ++a)
            #pragma unroll
            for (int b2 = 0; b2 < 6; ++b2)
                #pragma unroll
                for (int d2 = 0; d2 < 4; ++d2) c[a][b2][d2] = 0.f;

        #pragma unroll
        for (int kt = 0; kt < 4; ++kt) {
            int seg = kw * 8 + kt * 2 + segoff;
            uint32_t so = (uint32_t)((seg ^ lrow) << 4);
            uint32_t ah0[4], ah1[4], al0[4], al1[4];
            ldm4(ah0, rbh0 + so);
            ldm4(ah1, rbh1 + so);
            ldm4(al0, rbl0 + so);
            ldm4(al1, rbl1 + so);
            #pragma unroll
            for (int nt = 0; nt < 6; ++nt) {
                mma16816(c[0][nt], ah0, Bh[nt][kt][0], Bh[nt][kt][1]);
                mma16816(c[1][nt], ah1, Bh[nt][kt][0], Bh[nt][kt][1]);
                mma16816(c[0][nt], al0, Bh[nt][kt][0], Bh[nt][kt][1]);
                mma16816(c[1][nt], al1, Bh[nt][kt][0], Bh[nt][kt][1]);
                mma16816(c[0][nt], ah0, Bl[nt][kt][0], Bl[nt][kt][1]);
                mma16816(c[1][nt], ah1, Bl[nt][kt][0], Bl[nt][kt][1]);
            }
        }

        // store K-partials to SMEM
        {
            float* cb = (float*)(smc + CBUF);
            int rr = lane >> 2, cc = (lane & 3) * 2;
            #pragma unroll
            for (int mt = 0; mt < 2; ++mt)
                #pragma unroll
                for (int nt = 0; nt < 6; ++nt) {
                    int mm = mw * 32 + mt * 16 + rr;
                    int nn = nt * 8 + cc;
                    float* p0 = cb + mm * 212 + kw * 52 + nn;
                    *(float2*)p0 = make_float2(c[mt][nt][0], c[mt][nt][1]);
                    *(float2*)(p0 + 8 * 212) = make_float2(c[mt][nt][2], c[mt][nt][3]);
                }
        }
        __syncthreads();

        // ---- epilogue: reduce 4 K-partials, gates, h update ----
        float x0 = 0.f, x1 = 0.f, x2 = 0.f;
        if (enc) {
            const float* xp = X_p + bg * (TSZ * 3) + tt * 3;
            x0 = xp[0]; x1 = xp[1]; x2 = xp[2];
        } else if (tt > 0) {
            const float* xp = X_f + bg * (TSZ * 3) + (tt - 1) * 3;
            x0 = xp[0]; x1 = xp[1]; x2 = xp[2];
        }

        const float* cb = (float*)(smc + CBUF) + m_e * 212 + iq * 4;
        float4 sR = *(const float4*)(cb);
        float4 sZ = *(const float4*)(cb + 16);
        float4 sN = *(const float4*)(cb + 32);
        #pragma unroll
        for (int k2 = 1; k2 < 4; ++k2) {
            const float* p = cb + k2 * 52;
            float4 a = *(const float4*)(p);
            float4 b2 = *(const float4*)(p + 16);
            float4 d2 = *(const float4*)(p + 32);
            sR.x += a.x;  sR.y += a.y;  sR.z += a.z;  sR.w += a.w;
            sZ.x += b2.x; sZ.y += b2.y; sZ.z += b2.z; sZ.w += b2.w;
            sN.x += d2.x; sN.y += d2.y; sN.z += d2.z; sN.w += d2.w;
        }
        float sRa[4] = {sR.x, sR.y, sR.z, sR.w};
        float sZa[4] = {sZ.x, sZ.y, sZ.z, sZ.w};
        float sNa[4] = {sN.x, sN.y, sN.z, sN.w};
        float4 bR4 = *(const float4*)(bhh_s + iq * 4);
        float4 bZ4 = *(const float4*)(bhh_s + 16 + iq * 4);
        float4 bN4 = *(const float4*)(bhh_s + 32 + iq * 4);
        float bRa[4] = {bR4.x, bR4.y, bR4.z, bR4.w};
        float bZa[4] = {bZ4.x, bZ4.y, bZ4.z, bZ4.w};
        float bNa[4] = {bN4.x, bN4.y, bN4.z, bN4.w};

        const bool addn = (t == TSZ - 1);
        float h4[4];
        #pragma unroll
        for (int q = 0; q < 4; ++q) {
            int i = iq * 4 + q;
            float4 wR = wihb_s[i], wZ = wihb_s[16 + i], wN = wihb_s[32 + i];
            float xr = wR.w + wR.x * x0 + wR.y * x1 + wR.z * x2;
            float xz = wZ.w + wZ.x * x0 + wZ.y * x1 + wZ.z * x2;
            float xn = wN.w + wN.x * x0 + wN.y * x1 + wN.z * x2;
            float r = sigf(xr + sRa[q] + bRa[q]);
            float z = sigf(xz + sZa[q] + bZa[q]);
            float n = tanhf_(xn + r * (sNa[q] + bNa[q]));
            float h = n + z * (hprev[q] - n);
            if (addn) h += noise[bg * HSZ + ib * 16 + i];
            hprev[q] = h;
            h4[q] = h;
        }

        // write split h for next step
        {
            __nv_bfloat16 h0 = __float2bfloat16(h4[0]);
            __nv_bfloat16 h1 = __float2bfloat16(h4[1]);
            __nv_bfloat16 h2 = __float2bfloat16(h4[2]);
            __nv_bfloat16 h3 = __float2bfloat16(h4[3]);
            __nv_bfloat16 l0 = __float2bfloat16(h4[0] - __bfloat162float(h0));
            __nv_bfloat16 l1 = __float2bfloat16(h4[1] - __bfloat162float(h1));
            __nv_bfloat16 l2 = __float2bfloat16(h4[2] - __bfloat162float(h2));
            __nv_bfloat16 l3 = __float2bfloat16(h4[3] - __bfloat162float(h3));
            uint32_t hiA = (uint32_t)__bfloat16_as_ushort(h0)
                         | ((uint32_t)__bfloat16_as_ushort(h1) << 16);
            uint32_t hiB = (uint32_t)__bfloat16_as_ushort(h2)
                         | ((uint32_t)__bfloat16_as_ushort(h3) << 16);
            uint32_t loA = (uint32_t)__bfloat16_as_ushort(l0)
                         | ((uint32_t)__bfloat16_as_ushort(l1) << 16);
            uint32_t loB = (uint32_t)__bfloat16_as_ushort(l2)
                         | ((uint32_t)__bfloat16_as_ushort(l3) << 16);
            int off = bg * HSZ + ib * 16 + iq * 4;
            *(uint2*)(&g_hbf[0][nxt][off]) = make_uint2(hiA, hiB);
            *(uint2*)(&g_hbf[1][nxt][off]) = make_uint2(loA, loB);
        }

        // fused FC head partial (decoder)
        if (!enc) {
            float4 w0 = *(const float4*)(wfc_s + iq * 4);
            float4 w1 = *(const float4*)(wfc_s + 16 + iq * 4);
            float4 w2 = *(const float4*)(wfc_s + 32 + iq * 4);
            float y0 = h4[0] * w0.x + h4[1] * w0.y + h4[2] * w0.z + h4[3] * w0.w;
            float y1 = h4[0] * w1.x + h4[1] * w1.y + h4[2] * w1.z + h4[3] * w1.w;
            float y2 = h4[0] * w2.x + h4[1] * w2.y + h4[2] * w2.z + h4[3] * w2.w;
            y0 += __shfl_xor_sync(0xffffffffu, y0, 1);
            y0 += __shfl_xor_sync(0xffffffffu, y0, 2);
            y1 += __shfl_xor_sync(0xffffffffu, y1, 1);
            y1 += __shfl_xor_sync(0xffffffffu, y1, 2);
            y2 += __shfl_xor_sync(0xffffffffu, y2, 1);
            y2 += __shfl_xor_sync(0xffffffffu, y2, 2);
            if (iq == 0)
                *(float4*)(&g_yp[t & 1][blockIdx.x][m_e][0]) =
                    make_float4(y0, y1, y2, 0.f);
        }

        group_sync(bb, gen);
    }

    // final head reduction for tstep = 255 (partials written at t=511, par=1)
    if (ib == 0 && tid < 192) {
        int bl = tid / 3, d = tid - (tid / 3) * 3;
        float s2 = bfc[d];
        #pragma unroll
        for (int p = 0; p < 16; ++p)
            s2 += g_yp[1][bb * 16 + p][bl][d];
        out[((bb * 64 + bl) * TSZ + (TSZ - 1)) * 3 + d] = s2;
    }
}

extern "C" void kernel_launch(void* const* d_in, const int* in_sizes, int n_in,
                              void* d_out, int out_size) {
    const float* X_p   = (const float*)d_in[0];
    const float* X_f   = (const float*)d_in[1];
    const float* noise = (const float*)d_in[2];
    const float* Wih_e = (const float*)d_in[3];
    const float* Whh_e = (const float*)d_in[4];
    const float* bih_e = (const float*)d_in[5];
    const float* bhh_e = (const float*)d_in[6];
    const float* Wih_d = (const float*)d_in[7];
    const float* Whh_d = (const float*)d_in[8];
    const float* bih_d = (const float*)d_in[9];
    const float* bhh_d = (const float*)d_in[10];
    const float* Wfc   = (const float*)d_in[11];
    const float* bfc   = (const float*)d_in[12];
    float* out = (float*)d_out;

    cudaFuncSetAttribute(netg_mma, cudaFuncAttributeMaxDynamicSharedMemorySize,
                         SMEM_BYTES);
    netg_mma<<<NCTA, NTHR, SMEM_BYTES>>>(
        X_p, X_f, noise, Wih_e, Whh_e, bih_e, bhh_e,
        Wih_d, Whh_d, bih_d, bhh_d, Wfc, bfc, out);
}